// round 14
// baseline (speedup 1.0000x reference)
#include <cuda_runtime.h>
#include <cuda_bf16.h>
#include <cstdint>
#include <math.h>

#define B_   2
#define T_   2048
#define C_   2048
#define H_   16
#define D_   128
#define HALF_ 64
#define M_   (B_*T_)       // 4096
#define N1_  (3*C_)        // 6144
#define BH_  (B_*H_)       // 32

// ---------------- scratch (device globals) ----------------
__device__ float g_sin[T_ * HALF_];
__device__ float g_cos[T_ * HALF_];
__device__ __nv_bfloat16 g_qh[(size_t)BH_ * T_ * D_];
__device__ __nv_bfloat16 g_ql[(size_t)BH_ * T_ * D_];
__device__ __nv_bfloat16 g_kh[(size_t)BH_ * T_ * D_];
__device__ __nv_bfloat16 g_kl[(size_t)BH_ * T_ * D_];
__device__ __nv_bfloat16 g_vh[(size_t)BH_ * T_ * D_];
__device__ __nv_bfloat16 g_vl[(size_t)BH_ * T_ * D_];
__device__ __nv_bfloat16 g_xh[(size_t)M_ * C_];
__device__ __nv_bfloat16 g_xl[(size_t)M_ * C_];
__device__ __nv_bfloat16 g_w1h[(size_t)C_ * N1_];
__device__ __nv_bfloat16 g_w1l[(size_t)C_ * N1_];
__device__ __nv_bfloat16 g_w2h[(size_t)C_ * C_];
__device__ __nv_bfloat16 g_w2l[(size_t)C_ * C_];
__device__ __nv_bfloat16 g_oh[(size_t)M_ * C_];
__device__ __nv_bfloat16 g_ol[(size_t)M_ * C_];

// ---------------- fast exp (FFMA-pipe) --------------
__device__ __forceinline__ float fast_exp(float x) {
    x = fmaxf(x, -87.0f);
    float t = x * 1.4426950408889634f;
    int   i = __float2int_rn(t);
    float f = t - (float)i;
    float p =          1.3333558146428443e-3f;
    p = fmaf(p, f, 9.6181291780723730e-3f);
    p = fmaf(p, f, 5.5504108664821580e-2f);
    p = fmaf(p, f, 2.4022650695910072e-1f);
    p = fmaf(p, f, 6.9314718055994531e-1f);
    p = fmaf(p, f, 1.0f);
    return __int_as_float((i + 127) << 23) * p;
}

// ---------------- MMA / LDSM / cp.async primitives ----------------
#define LDSM_X4(R0,R1,R2,R3,ADDR) \
    asm volatile("ldmatrix.sync.aligned.m8n8.x4.shared.b16 {%0,%1,%2,%3}, [%4];" \
                 : "=r"(R0), "=r"(R1), "=r"(R2), "=r"(R3) : "r"(ADDR))
#define LDSM_X4_T(R0,R1,R2,R3,ADDR) \
    asm volatile("ldmatrix.sync.aligned.m8n8.x4.trans.shared.b16 {%0,%1,%2,%3}, [%4];" \
                 : "=r"(R0), "=r"(R1), "=r"(R2), "=r"(R3) : "r"(ADDR))
#define CP16(DST, SRC) \
    asm volatile("cp.async.cg.shared.global [%0], [%1], 16;" :: "r"(DST), "l"(SRC))
#define CP_COMMIT()  asm volatile("cp.async.commit_group;" ::: "memory")
#define CP_WAIT0()   asm volatile("cp.async.wait_group 0;" ::: "memory")
#define CP_WAIT1()   asm volatile("cp.async.wait_group 1;" ::: "memory")

__device__ __forceinline__ void mma16816(float* d, const unsigned* a, const unsigned* b) {
    asm volatile(
        "mma.sync.aligned.m16n8k16.row.col.f32.bf16.bf16.f32 "
        "{%0,%1,%2,%3}, {%4,%5,%6,%7}, {%8,%9}, {%0,%1,%2,%3};"
        : "+f"(d[0]), "+f"(d[1]), "+f"(d[2]), "+f"(d[3])
        : "r"(a[0]), "r"(a[1]), "r"(a[2]), "r"(a[3]), "r"(b[0]), "r"(b[1]));
}

__device__ __forceinline__ void split2(float x, float y, unsigned& hi, unsigned& lo) {
    __nv_bfloat162 h2 = __floats2bfloat162_rn(x, y);
    float hx = __bfloat162float(h2.x);
    float hy = __bfloat162float(h2.y);
    __nv_bfloat162 l2 = __floats2bfloat162_rn(x - hx, y - hy);
    hi = *reinterpret_cast<unsigned*>(&h2);
    lo = *reinterpret_cast<unsigned*>(&l2);
}

// =================================================================================
//  merged prep kernel: rope-table blocks first, then the three splits
// =================================================================================
#define PB_ROPE 512
#define PB_X    (M_ * C_ / 4 / 256)
#define PB_W1   ((size_t)C_ * N1_ / 4 / 256)
#define PB_W2   ((size_t)C_ * C_ / 4 / 256)
#define PB_TOTAL (PB_ROPE + PB_X + PB_W1 + PB_W2)

__device__ __forceinline__ void split_body(const float* __restrict__ src,
                                           __nv_bfloat16* __restrict__ th,
                                           __nv_bfloat16* __restrict__ tl, size_t blk)
{
    size_t i = (blk * 256 + threadIdx.x) * 4;
    float4 v = *(const float4*)(src + i);
    unsigned h0, l0, h1, l1;
    split2(v.x, v.y, h0, l0);
    split2(v.z, v.w, h1, l1);
    *(uint2*)(th + i) = make_uint2(h0, h1);
    *(uint2*)(tl + i) = make_uint2(l0, l1);
}

__global__ void prep_kernel(const float* __restrict__ x,
                            const float* __restrict__ Wqkv,
                            const float* __restrict__ Wout)
{
    size_t blk = blockIdx.x;
    if (blk < PB_ROPE) {
        int idx = (int)blk * 256 + threadIdx.x;
        int t = idx / HALF_, j = idx % HALF_;
        double div  = exp(-(double)(2 * j) * 9.210340371976184 / 128.0);
        float  divf = (float)div;
        float  angf = (float)t * divf;
        g_sin[idx] = (float)sin((double)angf);
        g_cos[idx] = (float)cos((double)angf);
        return;
    }
    blk -= PB_ROPE;
    if (blk < PB_X)  { split_body(x,    g_xh,  g_xl,  blk); return; }
    blk -= PB_X;
    if (blk < PB_W1) { split_body(Wqkv, g_w1h, g_w1l, blk); return; }
    blk -= PB_W1;
    split_body(Wout, g_w2h, g_w2l, blk);
}

// =================================================================================
//  bf16x3 split-precision tensor-core GEMM, PERSISTENT continuous cp.async pipeline.
//  B-operand warp columns split 16+16 (cols j and j+64 in same thread) so the
//  mode-1 RoPE epilogue is register-only (no smem reuse, pipeline never drains).
// =================================================================================
#define SGBH  16384
#define SGBL  24576
#define STAGE_ 32768
#define GSM_TOTAL (3 * STAGE_)
#define GEMM_GRID 296

__global__ void __launch_bounds__(256, 2) mma_gemm(const __nv_bfloat16* __restrict__ Ah,
                                                   const __nv_bfloat16* __restrict__ Al,
                                                   const __nv_bfloat16* __restrict__ Bh,
                                                   const __nv_bfloat16* __restrict__ Bl,
                                                   float* __restrict__ C,
                                                   int M, int N, int K, int mode)
{
    extern __shared__ char smem[];
    const uint32_t smem_u32 = (uint32_t)__cvta_generic_to_shared(smem);

    const int tid  = threadIdx.x;
    const int lane = tid & 31;
    const int wid  = tid >> 5;
    const int warp_m = wid & 1;
    const int warp_n = wid >> 1;
    const int quad = lane >> 3;
    const int rq   = lane & 7;
    const int lq   = lane & 3;

    // ---- tile-independent staging geometry ----
    uint32_t swA[4], swB[4];
    int raA[4], caA[4];
    int rbB[4], cbB[4], hlB[4];
#pragma unroll
    for (int i = 0; i < 4; i++) {
        int ia = i * 256 + tid;
        raA[i] = ia >> 3; caA[i] = ia & 7;
        swA[i] = raA[i] * 128 + ((caA[i] ^ (raA[i] & 7)) << 4);
        int hilo = ia >> 9;
        int rem  = ia & 511;
        rbB[i] = rem >> 4; cbB[i] = rem & 15; hlB[i] = hilo;
        swB[i] = (hilo ? SGBL : SGBH) + rbB[i] * 256 +
                 (((cbB[i] & 8) | ((cbB[i] & 7) ^ (rbB[i] & 7))) << 4);
    }

    // ---- ldmatrix lane addressing ----
    const int aRowL = warp_m * 64 + (quad & 1) * 8 + rq;
    const int kHalf = quad >> 1;
    const int arow7 = aRowL & 7;
    const int arowByte = aRowL * 128;

    const int kL = (quad & 1) * 8 + rq;
    int nbswp[2];
#pragma unroll
    for (int p = 0; p < 2; p++) {
        int nb = warp_n * 2 + (quad >> 1) + p * 8;   // split 16+16 column groups
        nbswp[p] = (nb & 8) | ((nb & 7) ^ (kL & 7));
    }
    const int bByteBase = kL * 256;

    const int MB = M >> 7;
    const int NT = MB * (N >> 7);
    const int KT = K >> 5;

    // ---- persistent issue-side state ----
    const __nv_bfloat16 *pA[4], *pB[4];
    int tile_i = blockIdx.x;

#define SET_PTRS(tile) do { \
    int bm_ = ((tile) % MB) * 128, bn_ = ((tile) / MB) * 128; \
    _Pragma("unroll") for (int i = 0; i < 4; i++) { \
        pA[i] = (caA[i] < 4 ? Ah : Al) + (size_t)(bm_ + raA[i]) * K + (caA[i] & 3) * 8; \
        pB[i] = (hlB[i] ? Bl : Bh) + (size_t)rbB[i] * N + bn_ + cbB[i] * 8; } } while (0)

#define G_ISS(k0, buf) do { \
    const uint32_t b_ = smem_u32 + (buf) * STAGE_; \
    _Pragma("unroll") for (int i = 0; i < 4; i++) { \
        CP16(b_ + swA[i], pA[i] + (k0)); \
        CP16(b_ + swB[i], pB[i] + (size_t)(k0) * N); } } while (0)

    SET_PTRS(tile_i);
    G_ISS(0, 0);  CP_COMMIT();
    G_ISS(32, 1); CP_COMMIT();
    int kt_i = 2;
    int sc = 0;                         // global compute-stage counter

    for (int tile_c = blockIdx.x; tile_c < NT; tile_c += gridDim.x) {
        float acc[4][4][4];
#pragma unroll
        for (int mt = 0; mt < 4; mt++)
#pragma unroll
            for (int nt = 0; nt < 4; nt++)
#pragma unroll
                for (int c = 0; c < 4; c++) acc[mt][nt][c] = 0.f;

        for (int kt = 0; kt < KT; kt++) {
            CP_WAIT1();
            __syncthreads();
            if (kt_i == KT) {
                tile_i += gridDim.x;
                kt_i = 0;
                if (tile_i < NT) SET_PTRS(tile_i);
            }
            if (tile_i < NT) G_ISS(kt_i * 32, (sc + 2) % 3);
            CP_COMMIT();
            kt_i++;

            const uint32_t sbase = smem_u32 + (sc % 3) * STAGE_;
#pragma unroll
            for (int kk = 0; kk < 2; kk++) {
                unsigned ah[4][4], al[4][4], bh[2][4], bl[2][4];
                const int chi = 2 * kk + kHalf;
                const int asw_h = ((chi)     ^ arow7) << 4;
                const int asw_l = ((chi + 4) ^ arow7) << 4;
#pragma unroll
                for (int mt = 0; mt < 4; mt++) {
                    uint32_t ad = sbase + arowByte + mt * 2048;
                    LDSM_X4(ah[mt][0], ah[mt][1], ah[mt][2], ah[mt][3], ad + asw_h);
                    LDSM_X4(al[mt][0], al[mt][1], al[mt][2], al[mt][3], ad + asw_l);
                }
#pragma unroll
                for (int p = 0; p < 2; p++) {
                    uint32_t bd = sbase + kk * 4096 + bByteBase + nbswp[p] * 16;
                    LDSM_X4_T(bh[p][0], bh[p][1], bh[p][2], bh[p][3], bd + SGBH);
                    LDSM_X4_T(bl[p][0], bl[p][1], bl[p][2], bl[p][3], bd + SGBL);
                }
#pragma unroll
                for (int mt = 0; mt < 4; mt++)
#pragma unroll
                    for (int nt = 0; nt < 4; nt++) {
                        const unsigned* bph = &bh[nt >> 1][(nt & 1) * 2];
                        const unsigned* bpl = &bl[nt >> 1][(nt & 1) * 2];
                        mma16816(acc[mt][nt], ah[mt], bph);
                        mma16816(acc[mt][nt], al[mt], bph);
                        mma16816(acc[mt][nt], ah[mt], bpl);
                    }
            }
            sc++;
        }

        // ---- register-only epilogue (no smem, no barrier) ----
        const int bm = (tile_c % MB) * 128;
        const int bn = (tile_c / MB) * 128;
        const int lr0 = warp_m * 64 + (lane >> 2);

        if (mode == 0) {
            const int r0 = bm + lr0;
            const int cb = bn + warp_n * 16 + lq * 2;
#pragma unroll
            for (int mt = 0; mt < 4; mt++)
#pragma unroll
                for (int nt = 0; nt < 4; nt++) {
                    int col = cb + (nt & 1) * 8 + (nt >> 1) * 64;
                    float* p0 = C + (size_t)(r0 + mt * 16) * N + col;
                    float* p1 = C + (size_t)(r0 + mt * 16 + 8) * N + col;
                    *(float2*)p0 = make_float2(acc[mt][nt][0], acc[mt][nt][1]);
                    *(float2*)p1 = make_float2(acc[mt][nt][2], acc[mt][nt][3]);
                }
            continue;
        }

        const int region = bn >> 11;            // 0=q 1=k 2=v
        const int head   = (bn & 2047) >> 7;
        __nv_bfloat16* dh = (region == 0) ? g_qh : (region == 1) ? g_kh : g_vh;
        __nv_bfloat16* dl = (region == 0) ? g_ql : (region == 1) ? g_kl : g_vl;
        const int cb0 = warp_n * 16 + lq * 2;

        if (region == 2) {
#pragma unroll
            for (int mt = 0; mt < 4; mt++)
#pragma unroll
                for (int rr = 0; rr < 2; rr++) {
                    int grow = bm + lr0 + mt * 16 + rr * 8;
                    int t = grow & (T_ - 1), b = grow >> 11;
                    size_t dst = ((size_t)(b * H_ + head) * T_ + t) * D_;
#pragma unroll
                    for (int nt = 0; nt < 4; nt++) {
                        int col = cb0 + (nt & 1) * 8 + (nt >> 1) * 64;
                        unsigned h, l;
                        split2(acc[mt][nt][2 * rr], acc[mt][nt][2 * rr + 1], h, l);
                        *(unsigned*)(dh + dst + col) = h;
                        *(unsigned*)(dl + dst + col) = l;
                    }
                }
            continue;
        }

        // Q/K: rope pairs (col j in acc[.][nt], col j+64 in acc[.][nt+2]) in registers
        const float qs = (region == 0) ? 0.088388347648318447f : 1.0f;
#pragma unroll
        for (int mt = 0; mt < 4; mt++)
#pragma unroll
            for (int rr = 0; rr < 2; rr++) {
                int grow = bm + lr0 + mt * 16 + rr * 8;
                int t = grow & (T_ - 1), b = grow >> 11;
                size_t dst = ((size_t)(b * H_ + head) * T_ + t) * D_;
#pragma unroll
                for (int nt = 0; nt < 2; nt++) {
                    int j = cb0 + nt * 8;                 // 0..63
                    float cs0 = g_cos[t * HALF_ + j],     sn0 = g_sin[t * HALF_ + j];
                    float cs1 = g_cos[t * HALF_ + j + 1], sn1 = g_sin[t * HALF_ + j + 1];
                    float a0 = acc[mt][nt][2 * rr],     a1 = acc[mt][nt][2 * rr + 1];
                    float b0 = acc[mt][nt + 2][2 * rr], b1 = acc[mt][nt + 2][2 * rr + 1];
                    float va0 = (a0 * cs0 - b0 * sn0) * qs;
                    float vb0 = (b0 * cs0 + a0 * sn0) * qs;
                    float va1 = (a1 * cs1 - b1 * sn1) * qs;
                    float vb1 = (b1 * cs1 + a1 * sn1) * qs;
                    unsigned h, l;
                    split2(va0, va1, h, l);
                    *(unsigned*)(dh + dst + j) = h;
                    *(unsigned*)(dl + dst + j) = l;
                    split2(vb0, vb1, h, l);
                    *(unsigned*)(dh + dst + j + 64) = h;
                    *(unsigned*)(dl + dst + j + 64) = l;
                }
            }
    }
#undef SET_PTRS
#undef G_ISS
}

// =================================================================================
//  Tensor-core causal flash attention (round-12 version: fused exp/pack into PV)
// =================================================================================
#define FKH 0
#define FKL 16384
#define FVH 32768
#define FVL 49152
#define FSTAGE 65536
#define FSM_TOTAL 131072

__device__ __forceinline__ uint32_t fsw(int r, int c) {
    return (uint32_t)(r * 256 + ((((c ^ r) & 7) | (c & 8)) << 4));
}

__global__ void __launch_bounds__(256, 1) flash_mma_kernel()
{
    extern __shared__ char fsm[];
    const uint32_t sb = (uint32_t)__cvta_generic_to_shared(fsm);

    const int i0  = (gridDim.x - 1) - blockIdx.x;
    const int bh  = blockIdx.y;
    const int tid = threadIdx.x;
    const int lane = tid & 31;
    const int w    = tid >> 5;
    const int quad = lane >> 3;
    const int rq   = lane & 7;
    const int lr   = lane >> 2;
    const int lq   = lane & 3;

    const size_t kvbase   = (size_t)bh * (T_ * D_);
    const size_t qrowbase = kvbase + (size_t)i0 * 128 * D_;

    {
        int r  = tid >> 1;
        int cb = (tid & 1) * 8;
        const size_t g = qrowbase + (size_t)r * D_;
#pragma unroll
        for (int j = 0; j < 8; j++) {
            int c = cb + j;
            uint32_t sw = fsw(r, c);
            *(uint4*)(fsm + sw)         = *(const uint4*)(g_qh + g + c * 8);
            *(uint4*)(fsm + 32768 + sw) = *(const uint4*)(g_ql + g + c * 8);
        }
    }
    __syncthreads();

    const int kvr  = tid >> 2;
    const int kvcb = (tid & 3) * 4;
    const int jmax = 2 * i0 + 1;
#define KV_ISSUE(J, BUF) do { \
    const size_t g_ = kvbase + (size_t)((J) * 64 + kvr) * D_; \
    const uint32_t base_ = sb + (BUF) * FSTAGE; \
    _Pragma("unroll") for (int j_ = 0; j_ < 4; j_++) { \
        int c_ = kvcb + j_; \
        uint32_t sw_ = fsw(kvr, c_); \
        CP16(base_ + FKH + sw_, g_kh + g_ + c_ * 8); \
        CP16(base_ + FKL + sw_, g_kl + g_ + c_ * 8); \
        CP16(base_ + FVH + sw_, g_vh + g_ + c_ * 8); \
        CP16(base_ + FVL + sw_, g_vl + g_ + c_ * 8); } \
    CP_COMMIT(); } while (0)

    KV_ISSUE(0, 1);

    const int arow  = 16 * w + (quad & 1) * 8 + rq;
    const int rB    = (quad & 1) * 8 + rq;
    const int cHalf = quad >> 1;

    unsigned qh[8][4], ql[8][4];
#pragma unroll
    for (int kk = 0; kk < 8; kk++) {
        uint32_t aaddr = sb + fsw(arow, 2 * kk + cHalf);
        LDSM_X4(qh[kk][0], qh[kk][1], qh[kk][2], qh[kk][3], aaddr);
        LDSM_X4(ql[kk][0], ql[kk][1], ql[kk][2], ql[kk][3], aaddr + 32768);
    }

    float o[16][4];
#pragma unroll
    for (int dt = 0; dt < 16; dt++)
#pragma unroll
        for (int e = 0; e < 4; e++) o[dt][e] = 0.f;
    float mcur[2] = {-3.4e38f, -3.4e38f};
    float lcur[2] = {0.f, 0.f};

    int buf = 1;
    for (int j0 = 0; j0 <= jmax; j0++) {
        CP_WAIT0();
        __syncthreads();
        if (j0 < jmax) KV_ISSUE(j0 + 1, buf ^ 1);

        const uint32_t kvb = sb + buf * FSTAGE;

        float s[8][4];
#pragma unroll
        for (int nt = 0; nt < 8; nt++)
#pragma unroll
            for (int e = 0; e < 4; e++) s[nt][e] = 0.f;

#pragma unroll
        for (int kk = 0; kk < 8; kk++) {
            const int ca = 2 * kk + cHalf;
            unsigned kh4[4][4], kl4[4][4];
#pragma unroll
            for (int p = 0; p < 4; p++) {
                uint32_t kaddr = kvb + fsw(16 * p + rB, ca);
                LDSM_X4(kh4[p][0], kh4[p][1], kh4[p][2], kh4[p][3], kaddr + FKH);
                LDSM_X4(kl4[p][0], kl4[p][1], kl4[p][2], kl4[p][3], kaddr + FKL);
            }
#pragma unroll
            for (int p = 0; p < 4; p++) {
                unsigned bh0[2] = {kh4[p][0], kh4[p][2]};
                unsigned bh1[2] = {kh4[p][1], kh4[p][3]};
                unsigned bl0[2] = {kl4[p][0], kl4[p][2]};
                unsigned bl1[2] = {kl4[p][1], kl4[p][3]};
                mma16816(s[2*p],   qh[kk], bh0);
                mma16816(s[2*p],   ql[kk], bh0);
                mma16816(s[2*p],   qh[kk], bl0);
                mma16816(s[2*p+1], qh[kk], bh1);
                mma16816(s[2*p+1], ql[kk], bh1);
                mma16816(s[2*p+1], qh[kk], bl1);
            }
        }

        if (j0 >= 2 * i0) {
            const int qr0 = i0 * 128 + 16 * w + lr;
            const int kc0 = j0 * 64 + 2 * lq;
#pragma unroll
            for (int nt = 0; nt < 8; nt++)
#pragma unroll
                for (int e = 0; e < 4; e++) {
                    int r = qr0 + (e >> 1) * 8;
                    int c = kc0 + 8 * nt + (e & 1);
                    if (c > r) s[nt][e] = -3.4e38f;
                }
        }

        float mn[2], alpha[2];
#pragma unroll
        for (int z = 0; z < 2; z++) {
            float mx = -3.4e38f;
#pragma unroll
            for (int nt = 0; nt < 8; nt++)
                mx = fmaxf(mx, fmaxf(s[nt][2*z], s[nt][2*z+1]));
            mx = fmaxf(mx, __shfl_xor_sync(0xffffffffu, mx, 1));
            mx = fmaxf(mx, __shfl_xor_sync(0xffffffffu, mx, 2));
            mn[z]    = fmaxf(mcur[z], mx);
            alpha[z] = fast_exp(mcur[z] - mn[z]);
            mcur[z]  = mn[z];
#pragma unroll
            for (int dt = 0; dt < 16; dt++) {
                o[dt][2*z]   *= alpha[z];
                o[dt][2*z+1] *= alpha[z];
            }
        }

        float ls0 = 0.f, ls1 = 0.f;
#pragma unroll
        for (int kk2 = 0; kk2 < 4; kk2++) {
            float e00 = fast_exp(s[2*kk2][0]   - mn[0]);
            float e01 = fast_exp(s[2*kk2][1]   - mn[0]);
            float e02 = fast_exp(s[2*kk2][2]   - mn[1]);
            float e03 = fast_exp(s[2*kk2][3]   - mn[1]);
            float e10 = fast_exp(s[2*kk2+1][0] - mn[0]);
            float e11 = fast_exp(s[2*kk2+1][1] - mn[0]);
            float e12 = fast_exp(s[2*kk2+1][2] - mn[1]);
            float e13 = fast_exp(s[2*kk2+1][3] - mn[1]);
            ls0 += e00 + e01 + e10 + e11;
            ls1 += e02 + e03 + e12 + e13;

            unsigned ph[4], pl[4];
            split2(e00, e01, ph[0], pl[0]);
            split2(e02, e03, ph[1], pl[1]);
            split2(e10, e11, ph[2], pl[2]);
            split2(e12, e13, ph[3], pl[3]);

            const int rV = 16 * kk2 + rB;
#pragma unroll
            for (int p = 0; p < 8; p++) {
                unsigned vh4[4], vl4[4];
                uint32_t vaddr = kvb + fsw(rV, 2 * p + cHalf);
                LDSM_X4_T(vh4[0], vh4[1], vh4[2], vh4[3], vaddr + FVH);
                LDSM_X4_T(vl4[0], vl4[1], vl4[2], vl4[3], vaddr + FVL);
                mma16816(o[2*p],   ph, &vh4[0]);
                mma16816(o[2*p],   pl, &vh4[0]);
                mma16816(o[2*p],   ph, &vl4[0]);
                mma16816(o[2*p+1], ph, &vh4[2]);
                mma16816(o[2*p+1], pl, &vh4[2]);
                mma16816(o[2*p+1], ph, &vl4[2]);
            }
        }

        ls0 += __shfl_xor_sync(0xffffffffu, ls0, 1);
        ls0 += __shfl_xor_sync(0xffffffffu, ls0, 2);
        ls1 += __shfl_xor_sync(0xffffffffu, ls1, 1);
        ls1 += __shfl_xor_sync(0xffffffffu, ls1, 2);
        lcur[0] = lcur[0] * alpha[0] + ls0;
        lcur[1] = lcur[1] * alpha[1] + ls1;

        buf ^= 1;
    }
#undef KV_ISSUE

    const float inv0 = 1.f / lcur[0];
    const float inv1 = 1.f / lcur[1];
    const size_t obase = ((size_t)bh * T_ + (size_t)i0 * 128 + 16 * w + lr) * D_;
#pragma unroll
    for (int dt = 0; dt < 16; dt++) {
        int col = 8 * dt + 2 * lq;
        unsigned h0, l0, h1, l1;
        split2(o[dt][0] * inv0, o[dt][1] * inv0, h0, l0);
        split2(o[dt][2] * inv1, o[dt][3] * inv1, h1, l1);
        *(unsigned*)(g_oh + obase + col)          = h0;
        *(unsigned*)(g_ol + obase + col)          = l0;
        *(unsigned*)(g_oh + obase + 8 * D_ + col) = h1;
        *(unsigned*)(g_ol + obase + 8 * D_ + col) = l1;
    }
}

// ---------------- launch ----------------
extern "C" void kernel_launch(void* const* d_in, const int* in_sizes, int n_in,
                              void* d_out, int out_size)
{
    const float* x    = (const float*)d_in[0];
    const float* Wqkv = (const float*)d_in[1];
    const float* Wout = (const float*)d_in[2];
    float* out = (float*)d_out;

    __nv_bfloat16 *xh, *xl, *w1h, *w1l, *w2h, *w2l, *oh, *ol;
    cudaGetSymbolAddress((void**)&xh,  g_xh);
    cudaGetSymbolAddress((void**)&xl,  g_xl);
    cudaGetSymbolAddress((void**)&w1h, g_w1h);
    cudaGetSymbolAddress((void**)&w1l, g_w1l);
    cudaGetSymbolAddress((void**)&w2h, g_w2h);
    cudaGetSymbolAddress((void**)&w2l, g_w2l);
    cudaGetSymbolAddress((void**)&oh,  g_oh);
    cudaGetSymbolAddress((void**)&ol,  g_ol);

    cudaFuncSetAttribute(mma_gemm, cudaFuncAttributeMaxDynamicSharedMemorySize, GSM_TOTAL);
    cudaFuncSetAttribute(flash_mma_kernel, cudaFuncAttributeMaxDynamicSharedMemorySize, FSM_TOTAL);

    // 0) merged prep
    prep_kernel<<<(unsigned)PB_TOTAL, 256>>>(x, Wqkv, Wout);
    // 1) QKV projection (persistent, fused register-only RoPE epilogue)
    mma_gemm<<<GEMM_GRID, 256, GSM_TOTAL>>>(xh, xl, w1h, w1l, nullptr, M_, N1_, C_, 1);
    // 2) flash attention (round-12 config)
    flash_mma_kernel<<<dim3(T_ / 128, BH_), 256, FSM_TOTAL>>>();
    // 3) output projection (persistent)
    mma_gemm<<<GEMM_GRID, 256, GSM_TOTAL>>>(oh, ol, w2h, w2l, out, M_, C_, C_, 0);
}

// round 15
// speedup vs baseline: 1.0156x; 1.0156x over previous
#include <cuda_runtime.h>
#include <cuda_bf16.h>
#include <cstdint>
#include <math.h>

#define B_   2
#define T_   2048
#define C_   2048
#define H_   16
#define D_   128
#define HALF_ 64
#define M_   (B_*T_)       // 4096
#define N1_  (3*C_)        // 6144
#define BH_  (B_*H_)       // 32

// ---------------- scratch (device globals) ----------------
__device__ float g_sin[T_ * HALF_];
__device__ float g_cos[T_ * HALF_];
__device__ __nv_bfloat16 g_qh[(size_t)BH_ * T_ * D_];
__device__ __nv_bfloat16 g_ql[(size_t)BH_ * T_ * D_];
__device__ __nv_bfloat16 g_kh[(size_t)BH_ * T_ * D_];
__device__ __nv_bfloat16 g_kl[(size_t)BH_ * T_ * D_];
__device__ __nv_bfloat16 g_vh[(size_t)BH_ * T_ * D_];
__device__ __nv_bfloat16 g_vl[(size_t)BH_ * T_ * D_];
__device__ __nv_bfloat16 g_xh[(size_t)M_ * C_];
__device__ __nv_bfloat16 g_xl[(size_t)M_ * C_];
__device__ __nv_bfloat16 g_w1h[(size_t)C_ * N1_];
__device__ __nv_bfloat16 g_w1l[(size_t)C_ * N1_];
__device__ __nv_bfloat16 g_w2h[(size_t)C_ * C_];
__device__ __nv_bfloat16 g_w2l[(size_t)C_ * C_];
__device__ __nv_bfloat16 g_oh[(size_t)M_ * C_];
__device__ __nv_bfloat16 g_ol[(size_t)M_ * C_];

// ---------------- fast exp (FFMA-pipe) --------------
__device__ __forceinline__ float fast_exp(float x) {
    x = fmaxf(x, -87.0f);
    float t = x * 1.4426950408889634f;
    int   i = __float2int_rn(t);
    float f = t - (float)i;
    float p =          1.3333558146428443e-3f;
    p = fmaf(p, f, 9.6181291780723730e-3f);
    p = fmaf(p, f, 5.5504108664821580e-2f);
    p = fmaf(p, f, 2.4022650695910072e-1f);
    p = fmaf(p, f, 6.9314718055994531e-1f);
    p = fmaf(p, f, 1.0f);
    return __int_as_float((i + 127) << 23) * p;
}

// ---------------- MMA / LDSM / cp.async primitives ----------------
#define LDSM_X4(R0,R1,R2,R3,ADDR) \
    asm volatile("ldmatrix.sync.aligned.m8n8.x4.shared.b16 {%0,%1,%2,%3}, [%4];" \
                 : "=r"(R0), "=r"(R1), "=r"(R2), "=r"(R3) : "r"(ADDR))
#define LDSM_X4_T(R0,R1,R2,R3,ADDR) \
    asm volatile("ldmatrix.sync.aligned.m8n8.x4.trans.shared.b16 {%0,%1,%2,%3}, [%4];" \
                 : "=r"(R0), "=r"(R1), "=r"(R2), "=r"(R3) : "r"(ADDR))
#define CP16(DST, SRC) \
    asm volatile("cp.async.cg.shared.global [%0], [%1], 16;" :: "r"(DST), "l"(SRC))
#define CP_COMMIT()  asm volatile("cp.async.commit_group;" ::: "memory")
#define CP_WAIT0()   asm volatile("cp.async.wait_group 0;" ::: "memory")
#define CP_WAIT1()   asm volatile("cp.async.wait_group 1;" ::: "memory")

__device__ __forceinline__ void mma16816(float* d, const unsigned* a, const unsigned* b) {
    asm volatile(
        "mma.sync.aligned.m16n8k16.row.col.f32.bf16.bf16.f32 "
        "{%0,%1,%2,%3}, {%4,%5,%6,%7}, {%8,%9}, {%0,%1,%2,%3};"
        : "+f"(d[0]), "+f"(d[1]), "+f"(d[2]), "+f"(d[3])
        : "r"(a[0]), "r"(a[1]), "r"(a[2]), "r"(a[3]), "r"(b[0]), "r"(b[1]));
}

__device__ __forceinline__ void split2(float x, float y, unsigned& hi, unsigned& lo) {
    __nv_bfloat162 h2 = __floats2bfloat162_rn(x, y);
    float hx = __bfloat162float(h2.x);
    float hy = __bfloat162float(h2.y);
    __nv_bfloat162 l2 = __floats2bfloat162_rn(x - hx, y - hy);
    hi = *reinterpret_cast<unsigned*>(&h2);
    lo = *reinterpret_cast<unsigned*>(&l2);
}

// =================================================================================
//  merged prep kernel: rope-table blocks first, then the three splits
// =================================================================================
#define PB_ROPE 512
#define PB_X    (M_ * C_ / 4 / 256)
#define PB_W1   ((size_t)C_ * N1_ / 4 / 256)
#define PB_W2   ((size_t)C_ * C_ / 4 / 256)
#define PB_TOTAL (PB_ROPE + PB_X + PB_W1 + PB_W2)

__device__ __forceinline__ void split_body(const float* __restrict__ src,
                                           __nv_bfloat16* __restrict__ th,
                                           __nv_bfloat16* __restrict__ tl, size_t blk)
{
    size_t i = (blk * 256 + threadIdx.x) * 4;
    float4 v = *(const float4*)(src + i);
    unsigned h0, l0, h1, l1;
    split2(v.x, v.y, h0, l0);
    split2(v.z, v.w, h1, l1);
    *(uint2*)(th + i) = make_uint2(h0, h1);
    *(uint2*)(tl + i) = make_uint2(l0, l1);
}

__global__ void prep_kernel(const float* __restrict__ x,
                            const float* __restrict__ Wqkv,
                            const float* __restrict__ Wout)
{
    size_t blk = blockIdx.x;
    if (blk < PB_ROPE) {
        int idx = (int)blk * 256 + threadIdx.x;
        int t = idx / HALF_, j = idx % HALF_;
        double div  = exp(-(double)(2 * j) * 9.210340371976184 / 128.0);
        float  divf = (float)div;
        float  angf = (float)t * divf;
        g_sin[idx] = (float)sin((double)angf);
        g_cos[idx] = (float)cos((double)angf);
        return;
    }
    blk -= PB_ROPE;
    if (blk < PB_X)  { split_body(x,    g_xh,  g_xl,  blk); return; }
    blk -= PB_X;
    if (blk < PB_W1) { split_body(Wqkv, g_w1h, g_w1l, blk); return; }
    blk -= PB_W1;
    split_body(Wout, g_w2h, g_w2l, blk);
}

// =================================================================================
//  bf16x3 split-precision tensor-core GEMM (cp.async 3-stage, BK=32, 2 CTAs/SM,
//  NON-persistent). B-operand warp columns split 16+16 so the mode-1 RoPE
//  epilogue is register-only (no smem roundtrip, no epilogue barrier).
// =================================================================================
#define SGBH  16384
#define SGBL  24576
#define STAGE_ 32768
#define NSTAGE 3
#define GSM_TOTAL (NSTAGE * STAGE_)

__global__ void __launch_bounds__(256, 2) mma_gemm(const __nv_bfloat16* __restrict__ Ah,
                                                   const __nv_bfloat16* __restrict__ Al,
                                                   const __nv_bfloat16* __restrict__ Bh,
                                                   const __nv_bfloat16* __restrict__ Bl,
                                                   float* __restrict__ C,
                                                   int M, int N, int K, int mode)
{
    extern __shared__ char smem[];
    const uint32_t smem_u32 = (uint32_t)__cvta_generic_to_shared(smem);

    const int tid  = threadIdx.x;
    const int lane = tid & 31;
    const int wid  = tid >> 5;
    const int warp_m = wid & 1;
    const int warp_n = wid >> 1;
    const int quad = lane >> 3;
    const int rq   = lane & 7;
    const int lq   = lane & 3;

    const int bm = blockIdx.y * 128;
    const int bn = blockIdx.x * 128;

    uint32_t swA[4], swB[4];
    const __nv_bfloat16* pA[4];
    const __nv_bfloat16* pB[4];
#pragma unroll
    for (int i = 0; i < 4; i++) {
        int ia = i * 256 + tid;
        int ra = ia >> 3, ca = ia & 7;
        swA[i] = ra * 128 + ((ca ^ (ra & 7)) << 4);
        pA[i]  = (ca < 4 ? Ah : Al) + (size_t)(bm + ra) * K + (ca & 3) * 8;
        int hilo = ia >> 9;
        int rem  = ia & 511;
        int rb = rem >> 4, cb = rem & 15;
        swB[i] = (hilo ? SGBL : SGBH) + rb * 256 + (((cb & 8) | ((cb & 7) ^ (rb & 7))) << 4);
        pB[i]  = (hilo ? Bl : Bh) + (size_t)rb * N + bn + cb * 8;
    }

    const int aRowL = warp_m * 64 + (quad & 1) * 8 + rq;
    const int kHalf = quad >> 1;
    const int arow7 = aRowL & 7;
    const int arowByte = aRowL * 128;

    const int kL = (quad & 1) * 8 + rq;
    int nbswp[2];
#pragma unroll
    for (int p = 0; p < 2; p++) {
        int nb = warp_n * 2 + (quad >> 1) + p * 8;    // split 16+16 column groups
        nbswp[p] = (nb & 8) | ((nb & 7) ^ (kL & 7));
    }
    const int bByteBase = kL * 256;

    float acc[4][4][4];
#pragma unroll
    for (int mt = 0; mt < 4; mt++)
#pragma unroll
        for (int nt = 0; nt < 4; nt++)
#pragma unroll
            for (int c = 0; c < 4; c++) acc[mt][nt][c] = 0.f;

#define G_ISSUE(k0, buf) do { \
    const uint32_t b_ = smem_u32 + (buf) * STAGE_; \
    _Pragma("unroll") for (int i = 0; i < 4; i++) { \
        CP16(b_ + swA[i], pA[i] + (k0)); \
        CP16(b_ + swB[i], pB[i] + (size_t)(k0) * N); } \
    CP_COMMIT(); } while (0)

    const int KT = K >> 5;
    G_ISSUE(0, 0);
    G_ISSUE(32, 1);

    for (int kt = 0; kt < KT; kt++) {
        if (kt + 1 < KT) { CP_WAIT1(); } else { CP_WAIT0(); }
        __syncthreads();
        if (kt + 2 < KT) G_ISSUE((kt + 2) * 32, (kt + 2) % NSTAGE);

        const uint32_t sbase = smem_u32 + (kt % NSTAGE) * STAGE_;
#pragma unroll
        for (int kk = 0; kk < 2; kk++) {
            unsigned ah[4][4], al[4][4], bh[2][4], bl[2][4];
            const int chi = 2 * kk + kHalf;
            const int asw_h = ((chi)     ^ arow7) << 4;
            const int asw_l = ((chi + 4) ^ arow7) << 4;
#pragma unroll
            for (int mt = 0; mt < 4; mt++) {
                uint32_t ad = sbase + arowByte + mt * 2048;
                LDSM_X4(ah[mt][0], ah[mt][1], ah[mt][2], ah[mt][3], ad + asw_h);
                LDSM_X4(al[mt][0], al[mt][1], al[mt][2], al[mt][3], ad + asw_l);
            }
#pragma unroll
            for (int p = 0; p < 2; p++) {
                uint32_t bd = sbase + kk * 4096 + bByteBase + nbswp[p] * 16;
                LDSM_X4_T(bh[p][0], bh[p][1], bh[p][2], bh[p][3], bd + SGBH);
                LDSM_X4_T(bl[p][0], bl[p][1], bl[p][2], bl[p][3], bd + SGBL);
            }
#pragma unroll
            for (int mt = 0; mt < 4; mt++)
#pragma unroll
                for (int nt = 0; nt < 4; nt++) {
                    const unsigned* bph = &bh[nt >> 1][(nt & 1) * 2];
                    const unsigned* bpl = &bl[nt >> 1][(nt & 1) * 2];
                    mma16816(acc[mt][nt], ah[mt], bph);
                    mma16816(acc[mt][nt], al[mt], bph);
                    mma16816(acc[mt][nt], ah[mt], bpl);
                }
        }
    }
#undef G_ISSUE

    // ---- register-only epilogues (no smem, no barrier) ----
    const int lr0 = warp_m * 64 + (lane >> 2);
    const int cb0 = warp_n * 16 + lq * 2;

    if (mode == 0) {
        const int r0 = bm + lr0;
        const int cb = bn + cb0;
#pragma unroll
        for (int mt = 0; mt < 4; mt++)
#pragma unroll
            for (int nt = 0; nt < 4; nt++) {
                int col = cb + (nt & 1) * 8 + (nt >> 1) * 64;
                float* p0 = C + (size_t)(r0 + mt * 16) * N + col;
                float* p1 = C + (size_t)(r0 + mt * 16 + 8) * N + col;
                *(float2*)p0 = make_float2(acc[mt][nt][0], acc[mt][nt][1]);
                *(float2*)p1 = make_float2(acc[mt][nt][2], acc[mt][nt][3]);
            }
        return;
    }

    const int region = bn >> 11;            // 0=q 1=k 2=v
    const int head   = (bn & 2047) >> 7;
    __nv_bfloat16* dh = (region == 0) ? g_qh : (region == 1) ? g_kh : g_vh;
    __nv_bfloat16* dl = (region == 0) ? g_ql : (region == 1) ? g_kl : g_vl;

    if (region == 2) {
#pragma unroll
        for (int mt = 0; mt < 4; mt++)
#pragma unroll
            for (int rr = 0; rr < 2; rr++) {
                int grow = bm + lr0 + mt * 16 + rr * 8;
                int t = grow & (T_ - 1), b = grow >> 11;
                size_t dst = ((size_t)(b * H_ + head) * T_ + t) * D_;
#pragma unroll
                for (int nt = 0; nt < 4; nt++) {
                    int col = cb0 + (nt & 1) * 8 + (nt >> 1) * 64;
                    unsigned h, l;
                    split2(acc[mt][nt][2 * rr], acc[mt][nt][2 * rr + 1], h, l);
                    *(unsigned*)(dh + dst + col) = h;
                    *(unsigned*)(dl + dst + col) = l;
                }
            }
        return;
    }

    // Q/K: rope pairs (col j in acc[.][nt], col j+64 in acc[.][nt+2]) in registers
    const float qs = (region == 0) ? 0.088388347648318447f : 1.0f;
#pragma unroll
    for (int mt = 0; mt < 4; mt++)
#pragma unroll
        for (int rr = 0; rr < 2; rr++) {
            int grow = bm + lr0 + mt * 16 + rr * 8;
            int t = grow & (T_ - 1), b = grow >> 11;
            size_t dst = ((size_t)(b * H_ + head) * T_ + t) * D_;
#pragma unroll
            for (int nt = 0; nt < 2; nt++) {
                int j = cb0 + nt * 8;                 // 0..63
                float cs0 = g_cos[t * HALF_ + j],     sn0 = g_sin[t * HALF_ + j];
                float cs1 = g_cos[t * HALF_ + j + 1], sn1 = g_sin[t * HALF_ + j + 1];
                float a0 = acc[mt][nt][2 * rr],     a1 = acc[mt][nt][2 * rr + 1];
                float b0 = acc[mt][nt + 2][2 * rr], b1 = acc[mt][nt + 2][2 * rr + 1];
                float va0 = (a0 * cs0 - b0 * sn0) * qs;
                float vb0 = (b0 * cs0 + a0 * sn0) * qs;
                float va1 = (a1 * cs1 - b1 * sn1) * qs;
                float vb1 = (b1 * cs1 + a1 * sn1) * qs;
                unsigned h, l;
                split2(va0, va1, h, l);
                *(unsigned*)(dh + dst + j) = h;
                *(unsigned*)(dl + dst + j) = l;
                split2(vb0, vb1, h, l);
                *(unsigned*)(dh + dst + j + 64) = h;
                *(unsigned*)(dl + dst + j + 64) = l;
            }
        }
}

// =================================================================================
//  Tensor-core causal flash attention (round-12 version: fused exp/pack into PV)
// =================================================================================
#define FKH 0
#define FKL 16384
#define FVH 32768
#define FVL 49152
#define FSTAGE 65536
#define FSM_TOTAL 131072

__device__ __forceinline__ uint32_t fsw(int r, int c) {
    return (uint32_t)(r * 256 + ((((c ^ r) & 7) | (c & 8)) << 4));
}

__global__ void __launch_bounds__(256, 1) flash_mma_kernel()
{
    extern __shared__ char fsm[];
    const uint32_t sb = (uint32_t)__cvta_generic_to_shared(fsm);

    const int i0  = (gridDim.x - 1) - blockIdx.x;
    const int bh  = blockIdx.y;
    const int tid = threadIdx.x;
    const int lane = tid & 31;
    const int w    = tid >> 5;
    const int quad = lane >> 3;
    const int rq   = lane & 7;
    const int lr   = lane >> 2;
    const int lq   = lane & 3;

    const size_t kvbase   = (size_t)bh * (T_ * D_);
    const size_t qrowbase = kvbase + (size_t)i0 * 128 * D_;

    {
        int r  = tid >> 1;
        int cb = (tid & 1) * 8;
        const size_t g = qrowbase + (size_t)r * D_;
#pragma unroll
        for (int j = 0; j < 8; j++) {
            int c = cb + j;
            uint32_t sw = fsw(r, c);
            *(uint4*)(fsm + sw)         = *(const uint4*)(g_qh + g + c * 8);
            *(uint4*)(fsm + 32768 + sw) = *(const uint4*)(g_ql + g + c * 8);
        }
    }
    __syncthreads();

    const int kvr  = tid >> 2;
    const int kvcb = (tid & 3) * 4;
    const int jmax = 2 * i0 + 1;
#define KV_ISSUE(J, BUF) do { \
    const size_t g_ = kvbase + (size_t)((J) * 64 + kvr) * D_; \
    const uint32_t base_ = sb + (BUF) * FSTAGE; \
    _Pragma("unroll") for (int j_ = 0; j_ < 4; j_++) { \
        int c_ = kvcb + j_; \
        uint32_t sw_ = fsw(kvr, c_); \
        CP16(base_ + FKH + sw_, g_kh + g_ + c_ * 8); \
        CP16(base_ + FKL + sw_, g_kl + g_ + c_ * 8); \
        CP16(base_ + FVH + sw_, g_vh + g_ + c_ * 8); \
        CP16(base_ + FVL + sw_, g_vl + g_ + c_ * 8); } \
    CP_COMMIT(); } while (0)

    KV_ISSUE(0, 1);

    const int arow  = 16 * w + (quad & 1) * 8 + rq;
    const int rB    = (quad & 1) * 8 + rq;
    const int cHalf = quad >> 1;

    unsigned qh[8][4], ql[8][4];
#pragma unroll
    for (int kk = 0; kk < 8; kk++) {
        uint32_t aaddr = sb + fsw(arow, 2 * kk + cHalf);
        LDSM_X4(qh[kk][0], qh[kk][1], qh[kk][2], qh[kk][3], aaddr);
        LDSM_X4(ql[kk][0], ql[kk][1], ql[kk][2], ql[kk][3], aaddr + 32768);
    }

    float o[16][4];
#pragma unroll
    for (int dt = 0; dt < 16; dt++)
#pragma unroll
        for (int e = 0; e < 4; e++) o[dt][e] = 0.f;
    float mcur[2] = {-3.4e38f, -3.4e38f};
    float lcur[2] = {0.f, 0.f};

    int buf = 1;
    for (int j0 = 0; j0 <= jmax; j0++) {
        CP_WAIT0();
        __syncthreads();
        if (j0 < jmax) KV_ISSUE(j0 + 1, buf ^ 1);

        const uint32_t kvb = sb + buf * FSTAGE;

        float s[8][4];
#pragma unroll
        for (int nt = 0; nt < 8; nt++)
#pragma unroll
            for (int e = 0; e < 4; e++) s[nt][e] = 0.f;

#pragma unroll
        for (int kk = 0; kk < 8; kk++) {
            const int ca = 2 * kk + cHalf;
            unsigned kh4[4][4], kl4[4][4];
#pragma unroll
            for (int p = 0; p < 4; p++) {
                uint32_t kaddr = kvb + fsw(16 * p + rB, ca);
                LDSM_X4(kh4[p][0], kh4[p][1], kh4[p][2], kh4[p][3], kaddr + FKH);
                LDSM_X4(kl4[p][0], kl4[p][1], kl4[p][2], kl4[p][3], kaddr + FKL);
            }
#pragma unroll
            for (int p = 0; p < 4; p++) {
                unsigned bh0[2] = {kh4[p][0], kh4[p][2]};
                unsigned bh1[2] = {kh4[p][1], kh4[p][3]};
                unsigned bl0[2] = {kl4[p][0], kl4[p][2]};
                unsigned bl1[2] = {kl4[p][1], kl4[p][3]};
                mma16816(s[2*p],   qh[kk], bh0);
                mma16816(s[2*p],   ql[kk], bh0);
                mma16816(s[2*p],   qh[kk], bl0);
                mma16816(s[2*p+1], qh[kk], bh1);
                mma16816(s[2*p+1], ql[kk], bh1);
                mma16816(s[2*p+1], qh[kk], bl1);
            }
        }

        if (j0 >= 2 * i0) {
            const int qr0 = i0 * 128 + 16 * w + lr;
            const int kc0 = j0 * 64 + 2 * lq;
#pragma unroll
            for (int nt = 0; nt < 8; nt++)
#pragma unroll
                for (int e = 0; e < 4; e++) {
                    int r = qr0 + (e >> 1) * 8;
                    int c = kc0 + 8 * nt + (e & 1);
                    if (c > r) s[nt][e] = -3.4e38f;
                }
        }

        float mn[2], alpha[2];
#pragma unroll
        for (int z = 0; z < 2; z++) {
            float mx = -3.4e38f;
#pragma unroll
            for (int nt = 0; nt < 8; nt++)
                mx = fmaxf(mx, fmaxf(s[nt][2*z], s[nt][2*z+1]));
            mx = fmaxf(mx, __shfl_xor_sync(0xffffffffu, mx, 1));
            mx = fmaxf(mx, __shfl_xor_sync(0xffffffffu, mx, 2));
            mn[z]    = fmaxf(mcur[z], mx);
            alpha[z] = fast_exp(mcur[z] - mn[z]);
            mcur[z]  = mn[z];
#pragma unroll
            for (int dt = 0; dt < 16; dt++) {
                o[dt][2*z]   *= alpha[z];
                o[dt][2*z+1] *= alpha[z];
            }
        }

        float ls0 = 0.f, ls1 = 0.f;
#pragma unroll
        for (int kk2 = 0; kk2 < 4; kk2++) {
            float e00 = fast_exp(s[2*kk2][0]   - mn[0]);
            float e01 = fast_exp(s[2*kk2][1]   - mn[0]);
            float e02 = fast_exp(s[2*kk2][2]   - mn[1]);
            float e03 = fast_exp(s[2*kk2][3]   - mn[1]);
            float e10 = fast_exp(s[2*kk2+1][0] - mn[0]);
            float e11 = fast_exp(s[2*kk2+1][1] - mn[0]);
            float e12 = fast_exp(s[2*kk2+1][2] - mn[1]);
            float e13 = fast_exp(s[2*kk2+1][3] - mn[1]);
            ls0 += e00 + e01 + e10 + e11;
            ls1 += e02 + e03 + e12 + e13;

            unsigned ph[4], pl[4];
            split2(e00, e01, ph[0], pl[0]);
            split2(e02, e03, ph[1], pl[1]);
            split2(e10, e11, ph[2], pl[2]);
            split2(e12, e13, ph[3], pl[3]);

            const int rV = 16 * kk2 + rB;
#pragma unroll
            for (int p = 0; p < 8; p++) {
                unsigned vh4[4], vl4[4];
                uint32_t vaddr = kvb + fsw(rV, 2 * p + cHalf);
                LDSM_X4_T(vh4[0], vh4[1], vh4[2], vh4[3], vaddr + FVH);
                LDSM_X4_T(vl4[0], vl4[1], vl4[2], vl4[3], vaddr + FVL);
                mma16816(o[2*p],   ph, &vh4[0]);
                mma16816(o[2*p],   pl, &vh4[0]);
                mma16816(o[2*p],   ph, &vl4[0]);
                mma16816(o[2*p+1], ph, &vh4[2]);
                mma16816(o[2*p+1], pl, &vh4[2]);
                mma16816(o[2*p+1], ph, &vl4[2]);
            }
        }

        ls0 += __shfl_xor_sync(0xffffffffu, ls0, 1);
        ls0 += __shfl_xor_sync(0xffffffffu, ls0, 2);
        ls1 += __shfl_xor_sync(0xffffffffu, ls1, 1);
        ls1 += __shfl_xor_sync(0xffffffffu, ls1, 2);
        lcur[0] = lcur[0] * alpha[0] + ls0;
        lcur[1] = lcur[1] * alpha[1] + ls1;

        buf ^= 1;
    }
#undef KV_ISSUE

    const float inv0 = 1.f / lcur[0];
    const float inv1 = 1.f / lcur[1];
    const size_t obase = ((size_t)bh * T_ + (size_t)i0 * 128 + 16 * w + lr) * D_;
#pragma unroll
    for (int dt = 0; dt < 16; dt++) {
        int col = 8 * dt + 2 * lq;
        unsigned h0, l0, h1, l1;
        split2(o[dt][0] * inv0, o[dt][1] * inv0, h0, l0);
        split2(o[dt][2] * inv1, o[dt][3] * inv1, h1, l1);
        *(unsigned*)(g_oh + obase + col)          = h0;
        *(unsigned*)(g_ol + obase + col)          = l0;
        *(unsigned*)(g_oh + obase + 8 * D_ + col) = h1;
        *(unsigned*)(g_ol + obase + 8 * D_ + col) = l1;
    }
}

// ---------------- launch ----------------
extern "C" void kernel_launch(void* const* d_in, const int* in_sizes, int n_in,
                              void* d_out, int out_size)
{
    const float* x    = (const float*)d_in[0];
    const float* Wqkv = (const float*)d_in[1];
    const float* Wout = (const float*)d_in[2];
    float* out = (float*)d_out;

    __nv_bfloat16 *xh, *xl, *w1h, *w1l, *w2h, *w2l, *oh, *ol;
    cudaGetSymbolAddress((void**)&xh,  g_xh);
    cudaGetSymbolAddress((void**)&xl,  g_xl);
    cudaGetSymbolAddress((void**)&w1h, g_w1h);
    cudaGetSymbolAddress((void**)&w1l, g_w1l);
    cudaGetSymbolAddress((void**)&w2h, g_w2h);
    cudaGetSymbolAddress((void**)&w2l, g_w2l);
    cudaGetSymbolAddress((void**)&oh,  g_oh);
    cudaGetSymbolAddress((void**)&ol,  g_ol);

    cudaFuncSetAttribute(mma_gemm, cudaFuncAttributeMaxDynamicSharedMemorySize, GSM_TOTAL);
    cudaFuncSetAttribute(flash_mma_kernel, cudaFuncAttributeMaxDynamicSharedMemorySize, FSM_TOTAL);

    // 0) merged prep
    prep_kernel<<<(unsigned)PB_TOTAL, 256>>>(x, Wqkv, Wout);
    // 1) QKV projection (register-only fused RoPE epilogue)
    mma_gemm<<<dim3(N1_ / 128, M_ / 128), 256, GSM_TOTAL>>>(xh, xl, w1h, w1l, nullptr, M_, N1_, C_, 1);
    // 2) flash attention (round-12 config)
    flash_mma_kernel<<<dim3(T_ / 128, BH_), 256, FSM_TOTAL>>>();
    // 3) output projection
    mma_gemm<<<dim3(C_ / 128, M_ / 128), 256, GSM_TOTAL>>>(oh, ol, w2h, w2l, out, M_, C_, C_, 0);
}

// round 17
// speedup vs baseline: 1.0263x; 1.0105x over previous
#include <cuda_runtime.h>
#include <cuda_bf16.h>
#include <cstdint>
#include <math.h>

#define B_   2
#define T_   2048
#define C_   2048
#define H_   16
#define D_   128
#define HALF_ 64
#define M_   (B_*T_)       // 4096
#define N1_  (3*C_)        // 6144
#define BH_  (B_*H_)       // 32

// ---------------- scratch (device globals) ----------------
__device__ float g_sin[T_ * HALF_];
__device__ float g_cos[T_ * HALF_];
__device__ __nv_bfloat16 g_qh[(size_t)BH_ * T_ * D_];
__device__ __nv_bfloat16 g_ql[(size_t)BH_ * T_ * D_];
__device__ __nv_bfloat16 g_kh[(size_t)BH_ * T_ * D_];
__device__ __nv_bfloat16 g_kl[(size_t)BH_ * T_ * D_];
__device__ __nv_bfloat16 g_vh[(size_t)BH_ * T_ * D_];
__device__ __nv_bfloat16 g_vl[(size_t)BH_ * T_ * D_];
__device__ __nv_bfloat16 g_xh[(size_t)M_ * C_];
__device__ __nv_bfloat16 g_xl[(size_t)M_ * C_];
__device__ __nv_bfloat16 g_w1h[(size_t)C_ * N1_];
__device__ __nv_bfloat16 g_w1l[(size_t)C_ * N1_];
__device__ __nv_bfloat16 g_w2h[(size_t)C_ * C_];
__device__ __nv_bfloat16 g_w2l[(size_t)C_ * C_];
__device__ __nv_bfloat16 g_oh[(size_t)M_ * C_];
__device__ __nv_bfloat16 g_ol[(size_t)M_ * C_];

// ---------------- fast exp (FFMA-pipe) --------------
__device__ __forceinline__ float fast_exp(float x) {
    x = fmaxf(x, -87.0f);
    float t = x * 1.4426950408889634f;
    int   i = __float2int_rn(t);
    float f = t - (float)i;
    float p =          1.3333558146428443e-3f;
    p = fmaf(p, f, 9.6181291780723730e-3f);
    p = fmaf(p, f, 5.5504108664821580e-2f);
    p = fmaf(p, f, 2.4022650695910072e-1f);
    p = fmaf(p, f, 6.9314718055994531e-1f);
    p = fmaf(p, f, 1.0f);
    return __int_as_float((i + 127) << 23) * p;
}

// ---------------- MMA / LDSM / cp.async primitives ----------------
#define LDSM_X4(R0,R1,R2,R3,ADDR) \
    asm volatile("ldmatrix.sync.aligned.m8n8.x4.shared.b16 {%0,%1,%2,%3}, [%4];" \
                 : "=r"(R0), "=r"(R1), "=r"(R2), "=r"(R3) : "r"(ADDR))
#define LDSM_X4_T(R0,R1,R2,R3,ADDR) \
    asm volatile("ldmatrix.sync.aligned.m8n8.x4.trans.shared.b16 {%0,%1,%2,%3}, [%4];" \
                 : "=r"(R0), "=r"(R1), "=r"(R2), "=r"(R3) : "r"(ADDR))
#define CP16(DST, SRC) \
    asm volatile("cp.async.cg.shared.global [%0], [%1], 16;" :: "r"(DST), "l"(SRC))
#define CP_COMMIT()  asm volatile("cp.async.commit_group;" ::: "memory")
#define CP_WAIT0()   asm volatile("cp.async.wait_group 0;" ::: "memory")
#define CP_WAIT1()   asm volatile("cp.async.wait_group 1;" ::: "memory")

__device__ __forceinline__ void mma16816(float* d, const unsigned* a, const unsigned* b) {
    asm volatile(
        "mma.sync.aligned.m16n8k16.row.col.f32.bf16.bf16.f32 "
        "{%0,%1,%2,%3}, {%4,%5,%6,%7}, {%8,%9}, {%0,%1,%2,%3};"
        : "+f"(d[0]), "+f"(d[1]), "+f"(d[2]), "+f"(d[3])
        : "r"(a[0]), "r"(a[1]), "r"(a[2]), "r"(a[3]), "r"(b[0]), "r"(b[1]));
}

__device__ __forceinline__ void split2(float x, float y, unsigned& hi, unsigned& lo) {
    __nv_bfloat162 h2 = __floats2bfloat162_rn(x, y);
    float hx = __bfloat162float(h2.x);
    float hy = __bfloat162float(h2.y);
    __nv_bfloat162 l2 = __floats2bfloat162_rn(x - hx, y - hy);
    hi = *reinterpret_cast<unsigned*>(&h2);
    lo = *reinterpret_cast<unsigned*>(&l2);
}

// =================================================================================
//  merged prep kernel: rope-table blocks first, then the three splits
// =================================================================================
#define PB_ROPE 512
#define PB_X    (M_ * C_ / 4 / 256)
#define PB_W1   ((size_t)C_ * N1_ / 4 / 256)
#define PB_W2   ((size_t)C_ * C_ / 4 / 256)
#define PB_TOTAL (PB_ROPE + PB_X + PB_W1 + PB_W2)

__device__ __forceinline__ void split_body(const float* __restrict__ src,
                                           __nv_bfloat16* __restrict__ th,
                                           __nv_bfloat16* __restrict__ tl, size_t blk)
{
    size_t i = (blk * 256 + threadIdx.x) * 4;
    float4 v = *(const float4*)(src + i);
    unsigned h0, l0, h1, l1;
    split2(v.x, v.y, h0, l0);
    split2(v.z, v.w, h1, l1);
    *(uint2*)(th + i) = make_uint2(h0, h1);
    *(uint2*)(tl + i) = make_uint2(l0, l1);
}

__global__ void prep_kernel(const float* __restrict__ x,
                            const float* __restrict__ Wqkv,
                            const float* __restrict__ Wout)
{
    size_t blk = blockIdx.x;
    if (blk < PB_ROPE) {
        int idx = (int)blk * 256 + threadIdx.x;
        int t = idx / HALF_, j = idx % HALF_;
        double div  = exp(-(double)(2 * j) * 9.210340371976184 / 128.0);
        float  divf = (float)div;
        float  angf = (float)t * divf;
        g_sin[idx] = (float)sin((double)angf);
        g_cos[idx] = (float)cos((double)angf);
        return;
    }
    blk -= PB_ROPE;
    if (blk < PB_X)  { split_body(x,    g_xh,  g_xl,  blk); return; }
    blk -= PB_X;
    if (blk < PB_W1) { split_body(Wqkv, g_w1h, g_w1l, blk); return; }
    blk -= PB_W1;
    split_body(Wout, g_w2h, g_w2l, blk);
}

// =================================================================================
//  bf16x3 split-precision tensor-core GEMM:
//  128 threads, 2x2 warp grid, 64x64 warp tiles (halved A/B LDSM redundancy),
//  cp.async 3-stage BK=32, 2 CTAs/SM, register-only fused RoPE epilogue (mode 1).
//  B regs from LDSM_X4_T pair CONSECUTIVELY: {0,1} = first n8, {2,3} = second n8.
// =================================================================================
#define SGBH  16384
#define SGBL  24576
#define STAGE_ 32768
#define NSTAGE 3
#define GSM_TOTAL (NSTAGE * STAGE_)

__global__ void __launch_bounds__(128, 2) mma_gemm(const __nv_bfloat16* __restrict__ Ah,
                                                   const __nv_bfloat16* __restrict__ Al,
                                                   const __nv_bfloat16* __restrict__ Bh,
                                                   const __nv_bfloat16* __restrict__ Bl,
                                                   float* __restrict__ C,
                                                   int M, int N, int K, int mode)
{
    extern __shared__ char smem[];
    const uint32_t smem_u32 = (uint32_t)__cvta_generic_to_shared(smem);

    const int tid  = threadIdx.x;
    const int lane = tid & 31;
    const int wid  = tid >> 5;          // 0..3
    const int warp_m = wid & 1;         // 64-row half
    const int warp_n = wid >> 1;        // 64-col half (interleaved groups)
    const int quad = lane >> 3;
    const int rq   = lane & 7;
    const int lq   = lane & 3;

    const int bm = blockIdx.y * 128;
    const int bn = blockIdx.x * 128;

    // ---- staging geometry ----
    const int caA = tid & 7;
    const int ra0 = tid >> 3;
    const uint32_t swA0 = ra0 * 128 + ((caA ^ (ra0 & 7)) << 4);
    const __nv_bfloat16* pAb = (caA < 4 ? Ah : Al) + (size_t)(bm + ra0) * K + (caA & 3) * 8;

    const int cbB = tid & 15;
    const int rb0 = tid >> 4;
    const uint32_t swB0 = rb0 * 256 + (((cbB & 8) | ((cbB & 7) ^ (rb0 & 7))) << 4);
    const __nv_bfloat16* pBh = Bh + (size_t)rb0 * N + bn + cbB * 8;
    const __nv_bfloat16* pBl = Bl + (size_t)rb0 * N + bn + cbB * 8;

    // ---- ldmatrix lane addressing ----
    const int aRowL = warp_m * 64 + (quad & 1) * 8 + rq;
    const int kHalf = quad >> 1;
    const int arow7 = aRowL & 7;
    const int arowByte = aRowL * 128;

    const int kL = (quad & 1) * 8 + rq;
    int nbswp[4];
#pragma unroll
    for (int p = 0; p < 4; p++) {
        int nb = warp_n * 2 + (quad >> 1) + p * 4;   // interleaved 16-col groups
        nbswp[p] = (nb & 8) | ((nb & 7) ^ (kL & 7));
    }
    const int bByteBase = kL * 256;

    float acc[4][8][4];
#pragma unroll
    for (int mt = 0; mt < 4; mt++)
#pragma unroll
        for (int nt = 0; nt < 8; nt++)
#pragma unroll
            for (int c = 0; c < 4; c++) acc[mt][nt][c] = 0.f;

#define G_ISSUE(k0, buf) do { \
    uint32_t bA_ = smem_u32 + (buf) * STAGE_ + swA0; \
    const __nv_bfloat16* gA_ = pAb + (k0); \
    _Pragma("unroll") for (int i = 0; i < 8; i++) \
        CP16(bA_ + i * 2048, gA_ + (size_t)(i * 16) * K); \
    uint32_t bH_ = smem_u32 + (buf) * STAGE_ + SGBH + swB0; \
    uint32_t bL_ = smem_u32 + (buf) * STAGE_ + SGBL + swB0; \
    const __nv_bfloat16* gH_ = pBh + (size_t)(k0) * N; \
    const __nv_bfloat16* gL_ = pBl + (size_t)(k0) * N; \
    _Pragma("unroll") for (int i = 0; i < 4; i++) { \
        CP16(bH_ + i * 2048, gH_ + (size_t)(i * 8) * N); \
        CP16(bL_ + i * 2048, gL_ + (size_t)(i * 8) * N); } \
    CP_COMMIT(); } while (0)

    const int KT = K >> 5;
    G_ISSUE(0, 0);
    G_ISSUE(32, 1);

    for (int kt = 0; kt < KT; kt++) {
        if (kt + 1 < KT) { CP_WAIT1(); } else { CP_WAIT0(); }
        __syncthreads();
        if (kt + 2 < KT) G_ISSUE((kt + 2) * 32, (kt + 2) % NSTAGE);

        const uint32_t sbase = smem_u32 + (kt % NSTAGE) * STAGE_;
#pragma unroll
        for (int kk = 0; kk < 2; kk++) {
            unsigned ah[4][4], al[4][4], bh[4][4], bl[4][4];
            const int chi = 2 * kk + kHalf;
            const int asw_h = ((chi)     ^ arow7) << 4;
            const int asw_l = ((chi + 4) ^ arow7) << 4;
#pragma unroll
            for (int mt = 0; mt < 4; mt++) {
                uint32_t ad = sbase + arowByte + mt * 2048;
                LDSM_X4(ah[mt][0], ah[mt][1], ah[mt][2], ah[mt][3], ad + asw_h);
                LDSM_X4(al[mt][0], al[mt][1], al[mt][2], al[mt][3], ad + asw_l);
            }
#pragma unroll
            for (int p = 0; p < 4; p++) {
                uint32_t bd = sbase + kk * 4096 + bByteBase + nbswp[p] * 16;
                LDSM_X4_T(bh[p][0], bh[p][1], bh[p][2], bh[p][3], bd + SGBH);
                LDSM_X4_T(bl[p][0], bl[p][1], bl[p][2], bl[p][3], bd + SGBL);
            }
#pragma unroll
            for (int mt = 0; mt < 4; mt++)
#pragma unroll
                for (int p = 0; p < 4; p++) {
                    // trans-LDSM: consecutive reg pairs per n8 group
                    mma16816(acc[mt][2*p],   ah[mt], &bh[p][0]);
                    mma16816(acc[mt][2*p],   al[mt], &bh[p][0]);
                    mma16816(acc[mt][2*p],   ah[mt], &bl[p][0]);
                    mma16816(acc[mt][2*p+1], ah[mt], &bh[p][2]);
                    mma16816(acc[mt][2*p+1], al[mt], &bh[p][2]);
                    mma16816(acc[mt][2*p+1], ah[mt], &bl[p][2]);
                }
        }
    }
#undef G_ISSUE

    // ---- register-only epilogues ----
    // col(nt) = warp_n*16 + lq*2 + (nt&1)*8 + (nt>>1)*32   (nt = 0..7)
    const int lr0 = warp_m * 64 + (lane >> 2);
    const int cb0 = warp_n * 16 + lq * 2;

    if (mode == 0) {
        const int r0 = bm + lr0;
#pragma unroll
        for (int mt = 0; mt < 4; mt++)
#pragma unroll
            for (int nt = 0; nt < 8; nt++) {
                int col = bn + cb0 + (nt & 1) * 8 + (nt >> 1) * 32;
                float* p0 = C + (size_t)(r0 + mt * 16) * N + col;
                float* p1 = C + (size_t)(r0 + mt * 16 + 8) * N + col;
                *(float2*)p0 = make_float2(acc[mt][nt][0], acc[mt][nt][1]);
                *(float2*)p1 = make_float2(acc[mt][nt][2], acc[mt][nt][3]);
            }
        return;
    }

    const int region = bn >> 11;            // 0=q 1=k 2=v
    const int head   = (bn & 2047) >> 7;
    __nv_bfloat16* dh = (region == 0) ? g_qh : (region == 1) ? g_kh : g_vh;
    __nv_bfloat16* dl = (region == 0) ? g_ql : (region == 1) ? g_kl : g_vl;

    if (region == 2) {
#pragma unroll
        for (int mt = 0; mt < 4; mt++)
#pragma unroll
            for (int rr = 0; rr < 2; rr++) {
                int grow = bm + lr0 + mt * 16 + rr * 8;
                int t = grow & (T_ - 1), b = grow >> 11;
                size_t dst = ((size_t)(b * H_ + head) * T_ + t) * D_;
#pragma unroll
                for (int nt = 0; nt < 8; nt++) {
                    int col = cb0 + (nt & 1) * 8 + (nt >> 1) * 32;
                    unsigned h, l;
                    split2(acc[mt][nt][2 * rr], acc[mt][nt][2 * rr + 1], h, l);
                    *(unsigned*)(dh + dst + col) = h;
                    *(unsigned*)(dl + dst + col) = l;
                }
            }
        return;
    }

    // Q/K: rope pairs — col j in acc[.][nt] (nt 0..3), col j+64 in acc[.][nt+4]
    const float qs = (region == 0) ? 0.088388347648318447f : 1.0f;
#pragma unroll
    for (int mt = 0; mt < 4; mt++)
#pragma unroll
        for (int rr = 0; rr < 2; rr++) {
            int grow = bm + lr0 + mt * 16 + rr * 8;
            int t = grow & (T_ - 1), b = grow >> 11;
            size_t dst = ((size_t)(b * H_ + head) * T_ + t) * D_;
#pragma unroll
            for (int nt = 0; nt < 4; nt++) {
                int j = cb0 + (nt & 1) * 8 + (nt >> 1) * 32;   // 0..63
                float cs0 = g_cos[t * HALF_ + j],     sn0 = g_sin[t * HALF_ + j];
                float cs1 = g_cos[t * HALF_ + j + 1], sn1 = g_sin[t * HALF_ + j + 1];
                float a0 = acc[mt][nt][2 * rr],     a1 = acc[mt][nt][2 * rr + 1];
                float b0 = acc[mt][nt + 4][2 * rr], b1 = acc[mt][nt + 4][2 * rr + 1];
                float va0 = (a0 * cs0 - b0 * sn0) * qs;
                float vb0 = (b0 * cs0 + a0 * sn0) * qs;
                float va1 = (a1 * cs1 - b1 * sn1) * qs;
                float vb1 = (b1 * cs1 + a1 * sn1) * qs;
                unsigned h, l;
                split2(va0, va1, h, l);
                *(unsigned*)(dh + dst + j) = h;
                *(unsigned*)(dl + dst + j) = l;
                split2(vb0, vb1, h, l);
                *(unsigned*)(dh + dst + j + 64) = h;
                *(unsigned*)(dl + dst + j + 64) = l;
            }
        }
}

// =================================================================================
//  Tensor-core causal flash attention (round-12 version: fused exp/pack into PV)
// =================================================================================
#define FKH 0
#define FKL 16384
#define FVH 32768
#define FVL 49152
#define FSTAGE 65536
#define FSM_TOTAL 131072

__device__ __forceinline__ uint32_t fsw(int r, int c) {
    return (uint32_t)(r * 256 + ((((c ^ r) & 7) | (c & 8)) << 4));
}

__global__ void __launch_bounds__(256, 1) flash_mma_kernel()
{
    extern __shared__ char fsm[];
    const uint32_t sb = (uint32_t)__cvta_generic_to_shared(fsm);

    const int i0  = (gridDim.x - 1) - blockIdx.x;
    const int bh  = blockIdx.y;
    const int tid = threadIdx.x;
    const int lane = tid & 31;
    const int w    = tid >> 5;
    const int quad = lane >> 3;
    const int rq   = lane & 7;
    const int lr   = lane >> 2;
    const int lq   = lane & 3;

    const size_t kvbase   = (size_t)bh * (T_ * D_);
    const size_t qrowbase = kvbase + (size_t)i0 * 128 * D_;

    {
        int r  = tid >> 1;
        int cb = (tid & 1) * 8;
        const size_t g = qrowbase + (size_t)r * D_;
#pragma unroll
        for (int j = 0; j < 8; j++) {
            int c = cb + j;
            uint32_t sw = fsw(r, c);
            *(uint4*)(fsm + sw)         = *(const uint4*)(g_qh + g + c * 8);
            *(uint4*)(fsm + 32768 + sw) = *(const uint4*)(g_ql + g + c * 8);
        }
    }
    __syncthreads();

    const int kvr  = tid >> 2;
    const int kvcb = (tid & 3) * 4;
    const int jmax = 2 * i0 + 1;
#define KV_ISSUE(J, BUF) do { \
    const size_t g_ = kvbase + (size_t)((J) * 64 + kvr) * D_; \
    const uint32_t base_ = sb + (BUF) * FSTAGE; \
    _Pragma("unroll") for (int j_ = 0; j_ < 4; j_++) { \
        int c_ = kvcb + j_; \
        uint32_t sw_ = fsw(kvr, c_); \
        CP16(base_ + FKH + sw_, g_kh + g_ + c_ * 8); \
        CP16(base_ + FKL + sw_, g_kl + g_ + c_ * 8); \
        CP16(base_ + FVH + sw_, g_vh + g_ + c_ * 8); \
        CP16(base_ + FVL + sw_, g_vl + g_ + c_ * 8); } \
    CP_COMMIT(); } while (0)

    KV_ISSUE(0, 1);

    const int arow  = 16 * w + (quad & 1) * 8 + rq;
    const int rB    = (quad & 1) * 8 + rq;
    const int cHalf = quad >> 1;

    unsigned qh[8][4], ql[8][4];
#pragma unroll
    for (int kk = 0; kk < 8; kk++) {
        uint32_t aaddr = sb + fsw(arow, 2 * kk + cHalf);
        LDSM_X4(qh[kk][0], qh[kk][1], qh[kk][2], qh[kk][3], aaddr);
        LDSM_X4(ql[kk][0], ql[kk][1], ql[kk][2], ql[kk][3], aaddr + 32768);
    }

    float o[16][4];
#pragma unroll
    for (int dt = 0; dt < 16; dt++)
#pragma unroll
        for (int e = 0; e < 4; e++) o[dt][e] = 0.f;
    float mcur[2] = {-3.4e38f, -3.4e38f};
    float lcur[2] = {0.f, 0.f};

    int buf = 1;
    for (int j0 = 0; j0 <= jmax; j0++) {
        CP_WAIT0();
        __syncthreads();
        if (j0 < jmax) KV_ISSUE(j0 + 1, buf ^ 1);

        const uint32_t kvb = sb + buf * FSTAGE;

        float s[8][4];
#pragma unroll
        for (int nt = 0; nt < 8; nt++)
#pragma unroll
            for (int e = 0; e < 4; e++) s[nt][e] = 0.f;

#pragma unroll
        for (int kk = 0; kk < 8; kk++) {
            const int ca = 2 * kk + cHalf;
            unsigned kh4[4][4], kl4[4][4];
#pragma unroll
            for (int p = 0; p < 4; p++) {
                uint32_t kaddr = kvb + fsw(16 * p + rB, ca);
                LDSM_X4(kh4[p][0], kh4[p][1], kh4[p][2], kh4[p][3], kaddr + FKH);
                LDSM_X4(kl4[p][0], kl4[p][1], kl4[p][2], kl4[p][3], kaddr + FKL);
            }
#pragma unroll
            for (int p = 0; p < 4; p++) {
                unsigned bh0[2] = {kh4[p][0], kh4[p][2]};
                unsigned bh1[2] = {kh4[p][1], kh4[p][3]};
                unsigned bl0[2] = {kl4[p][0], kl4[p][2]};
                unsigned bl1[2] = {kl4[p][1], kl4[p][3]};
                mma16816(s[2*p],   qh[kk], bh0);
                mma16816(s[2*p],   ql[kk], bh0);
                mma16816(s[2*p],   qh[kk], bl0);
                mma16816(s[2*p+1], qh[kk], bh1);
                mma16816(s[2*p+1], ql[kk], bh1);
                mma16816(s[2*p+1], qh[kk], bl1);
            }
        }

        if (j0 >= 2 * i0) {
            const int qr0 = i0 * 128 + 16 * w + lr;
            const int kc0 = j0 * 64 + 2 * lq;
#pragma unroll
            for (int nt = 0; nt < 8; nt++)
#pragma unroll
                for (int e = 0; e < 4; e++) {
                    int r = qr0 + (e >> 1) * 8;
                    int c = kc0 + 8 * nt + (e & 1);
                    if (c > r) s[nt][e] = -3.4e38f;
                }
        }

        float mn[2], alpha[2];
#pragma unroll
        for (int z = 0; z < 2; z++) {
            float mx = -3.4e38f;
#pragma unroll
            for (int nt = 0; nt < 8; nt++)
                mx = fmaxf(mx, fmaxf(s[nt][2*z], s[nt][2*z+1]));
            mx = fmaxf(mx, __shfl_xor_sync(0xffffffffu, mx, 1));
            mx = fmaxf(mx, __shfl_xor_sync(0xffffffffu, mx, 2));
            mn[z]    = fmaxf(mcur[z], mx);
            alpha[z] = fast_exp(mcur[z] - mn[z]);
            mcur[z]  = mn[z];
#pragma unroll
            for (int dt = 0; dt < 16; dt++) {
                o[dt][2*z]   *= alpha[z];
                o[dt][2*z+1] *= alpha[z];
            }
        }

        float ls0 = 0.f, ls1 = 0.f;
#pragma unroll
        for (int kk2 = 0; kk2 < 4; kk2++) {
            float e00 = fast_exp(s[2*kk2][0]   - mn[0]);
            float e01 = fast_exp(s[2*kk2][1]   - mn[0]);
            float e02 = fast_exp(s[2*kk2][2]   - mn[1]);
            float e03 = fast_exp(s[2*kk2][3]   - mn[1]);
            float e10 = fast_exp(s[2*kk2+1][0] - mn[0]);
            float e11 = fast_exp(s[2*kk2+1][1] - mn[0]);
            float e12 = fast_exp(s[2*kk2+1][2] - mn[1]);
            float e13 = fast_exp(s[2*kk2+1][3] - mn[1]);
            ls0 += e00 + e01 + e10 + e11;
            ls1 += e02 + e03 + e12 + e13;

            unsigned ph[4], pl[4];
            split2(e00, e01, ph[0], pl[0]);
            split2(e02, e03, ph[1], pl[1]);
            split2(e10, e11, ph[2], pl[2]);
            split2(e12, e13, ph[3], pl[3]);

            const int rV = 16 * kk2 + rB;
#pragma unroll
            for (int p = 0; p < 8; p++) {
                unsigned vh4[4], vl4[4];
                uint32_t vaddr = kvb + fsw(rV, 2 * p + cHalf);
                LDSM_X4_T(vh4[0], vh4[1], vh4[2], vh4[3], vaddr + FVH);
                LDSM_X4_T(vl4[0], vl4[1], vl4[2], vl4[3], vaddr + FVL);
                mma16816(o[2*p],   ph, &vh4[0]);
                mma16816(o[2*p],   pl, &vh4[0]);
                mma16816(o[2*p],   ph, &vl4[0]);
                mma16816(o[2*p+1], ph, &vh4[2]);
                mma16816(o[2*p+1], pl, &vh4[2]);
                mma16816(o[2*p+1], ph, &vl4[2]);
            }
        }

        ls0 += __shfl_xor_sync(0xffffffffu, ls0, 1);
        ls0 += __shfl_xor_sync(0xffffffffu, ls0, 2);
        ls1 += __shfl_xor_sync(0xffffffffu, ls1, 1);
        ls1 += __shfl_xor_sync(0xffffffffu, ls1, 2);
        lcur[0] = lcur[0] * alpha[0] + ls0;
        lcur[1] = lcur[1] * alpha[1] + ls1;

        buf ^= 1;
    }
#undef KV_ISSUE

    const float inv0 = 1.f / lcur[0];
    const float inv1 = 1.f / lcur[1];
    const size_t obase = ((size_t)bh * T_ + (size_t)i0 * 128 + 16 * w + lr) * D_;
#pragma unroll
    for (int dt = 0; dt < 16; dt++) {
        int col = 8 * dt + 2 * lq;
        unsigned h0, l0, h1, l1;
        split2(o[dt][0] * inv0, o[dt][1] * inv0, h0, l0);
        split2(o[dt][2] * inv1, o[dt][3] * inv1, h1, l1);
        *(unsigned*)(g_oh + obase + col)          = h0;
        *(unsigned*)(g_ol + obase + col)          = l0;
        *(unsigned*)(g_oh + obase + 8 * D_ + col) = h1;
        *(unsigned*)(g_ol + obase + 8 * D_ + col) = l1;
    }
}

// ---------------- launch ----------------
extern "C" void kernel_launch(void* const* d_in, const int* in_sizes, int n_in,
                              void* d_out, int out_size)
{
    const float* x    = (const float*)d_in[0];
    const float* Wqkv = (const float*)d_in[1];
    const float* Wout = (const float*)d_in[2];
    float* out = (float*)d_out;

    __nv_bfloat16 *xh, *xl, *w1h, *w1l, *w2h, *w2l, *oh, *ol;
    cudaGetSymbolAddress((void**)&xh,  g_xh);
    cudaGetSymbolAddress((void**)&xl,  g_xl);
    cudaGetSymbolAddress((void**)&w1h, g_w1h);
    cudaGetSymbolAddress((void**)&w1l, g_w1l);
    cudaGetSymbolAddress((void**)&w2h, g_w2h);
    cudaGetSymbolAddress((void**)&w2l, g_w2l);
    cudaGetSymbolAddress((void**)&oh,  g_oh);
    cudaGetSymbolAddress((void**)&ol,  g_ol);

    cudaFuncSetAttribute(mma_gemm, cudaFuncAttributeMaxDynamicSharedMemorySize, GSM_TOTAL);
    cudaFuncSetAttribute(flash_mma_kernel, cudaFuncAttributeMaxDynamicSharedMemorySize, FSM_TOTAL);

    // 0) merged prep
    prep_kernel<<<(unsigned)PB_TOTAL, 256>>>(x, Wqkv, Wout);
    // 1) QKV projection (64x64 warp tiles, register-only fused RoPE epilogue)
    mma_gemm<<<dim3(N1_ / 128, M_ / 128), 128, GSM_TOTAL>>>(xh, xl, w1h, w1l, nullptr, M_, N1_, C_, 1);
    // 2) flash attention (round-12 config)
    flash_mma_kernel<<<dim3(T_ / 128, BH_), 256, FSM_TOTAL>>>();
    // 3) output projection
    mma_gemm<<<dim3(C_ / 128, M_ / 128), 128, GSM_TOTAL>>>(oh, ol, w2h, w2l, out, M_, C_, C_, 0);
}